// round 4
// baseline (speedup 1.0000x reference)
#include <cuda_runtime.h>
#include <cuda_bf16.h>

// ---------------------------------------------------------------------------
// Simplex4Net: B=32, N=64, D=64
//   kA: projections; kB: six Gram matrices * 0.0625
//   kC: persistent blocks over 4096 tiles (b, i, j-half); thread=(k, l-quad)
//   kD: reduce + gelu MLP head
// ---------------------------------------------------------------------------

#define BSZ 32
#define NP  64
#define DD  64
#define GRID_C 592          // 4 * 148
#define NTILES 4096         // 32 b * 64 i * 2 jh

__device__ float g_K[4][BSZ][NP * DD];
__device__ float g_E[6][BSZ][NP * NP];   // 0:(i,j) 1:(i,k) 2:(i,l) 3:(j,k) 4:(j,l) 5:(l,k)^T
__device__ float g_anchor[2][BSZ * NP];  // [jh][b*64+i]

typedef unsigned long long ull;

__device__ __forceinline__ ull pk2(float lo, float hi) {
    ull r; asm("mov.b64 %0, {%1, %2};" : "=l"(r) : "f"(lo), "f"(hi)); return r;
}
__device__ __forceinline__ void upk2(ull v, float& lo, float& hi) {
    asm("mov.b64 {%0, %1}, %2;" : "=f"(lo), "=f"(hi) : "l"(v));
}
__device__ __forceinline__ ull add2(ull a, ull b) {
    ull r; asm("add.rn.f32x2 %0, %1, %2;" : "=l"(r) : "l"(a), "l"(b)); return r;
}
__device__ __forceinline__ ull mul2(ull a, ull b) {
    ull r; asm("mul.rn.f32x2 %0, %1, %2;" : "=l"(r) : "l"(a), "l"(b)); return r;
}
__device__ __forceinline__ ull fma2(ull a, ull b, ull c) {
    ull r; asm("fma.rn.f32x2 %0, %1, %2, %3;" : "=l"(r) : "l"(a), "l"(b), "l"(c)); return r;
}
__device__ __forceinline__ float tanhax(float x) {
    float y; asm("tanh.approx.f32 %0, %1;" : "=f"(y) : "f"(x)); return y;
}

// ---------------------------------------------------------------------------
__global__ void kA(const float* __restrict__ pc,
                   const float* __restrict__ Wq,  const float* __restrict__ bq,
                   const float* __restrict__ Wk1, const float* __restrict__ bk1,
                   const float* __restrict__ Wk2, const float* __restrict__ bk2,
                   const float* __restrict__ Wk3, const float* __restrict__ bk3)
{
    int b = blockIdx.x;
    __shared__ float sp[NP * 3];
    __shared__ float sW[4][3 * DD];
    __shared__ float sb[4][DD];
    int t = threadIdx.x;
    if (t < 192) {
        sp[t]    = pc[b * 192 + t];
        sW[0][t] = Wq[t];
        sW[1][t] = Wk1[t];
        sW[2][t] = Wk2[t];
        sW[3][t] = Wk3[t];
    }
    if (t < 64) {
        sb[0][t] = bq[t]; sb[1][t] = bk1[t]; sb[2][t] = bk2[t]; sb[3][t] = bk3[t];
    }
    __syncthreads();
    for (int m = 0; m < 4; m++) {
        const float* W = sW[m];
        const float* bb = sb[m];
        for (int idx = t; idx < NP * DD; idx += 256) {
            int n = idx >> 6, d = idx & 63;
            float v = bb[d]
                    + sp[n * 3 + 0] * W[d]
                    + sp[n * 3 + 1] * W[64 + d]
                    + sp[n * 3 + 2] * W[128 + d];
            g_K[m][b][idx] = v;
        }
    }
}

// ---------------------------------------------------------------------------
__global__ void kB()
{
    int p = blockIdx.x, b = blockIdx.y;
    const int XI[6] = {0, 0, 0, 1, 1, 3};
    const int YI[6] = {1, 2, 3, 2, 3, 2};
    __shared__ float sX[NP][65];
    __shared__ float sY[NP][65];
    int t = threadIdx.x;
    const float* X = g_K[XI[p]][b];
    const float* Y = g_K[YI[p]][b];
    for (int idx = t; idx < NP * DD; idx += 256) {
        sX[idx >> 6][idx & 63] = X[idx];
        sY[idx >> 6][idx & 63] = Y[idx];
    }
    __syncthreads();
    for (int idx = t; idx < NP * NP; idx += 256) {
        int n = idx >> 6, m = idx & 63;
        float s = 0.f;
        #pragma unroll
        for (int d = 0; d < DD; d++)
            s = fmaf(sX[n][d], sY[m][d], s);
        g_E[p][b][idx] = s * 0.0625f;
    }
}

// ---------------------------------------------------------------------------
// Kernel C: persistent. 592 blocks x 256 threads; tiles = (b, i, jh).
// Per tile: j in [jh*32, jh*32+32). Thread = (k = t&63, l-quad per unit).
//
// SA2[jl][k]  (ull)        = {a,a}, a = E3[j][k] + E0[i][j],  jl = j - jh*32
// SB4[jl][lq] (ulonglong2) = b(l) = E4[j][l] + E2[i][l], 4 per lq
// DJ[jp][6]   (ull)        = {x,x},{y,y},{z,z} for local j=2jp, 2jp+1
// ---------------------------------------------------------------------------
__global__ void __launch_bounds__(256, 4) kC(const float* __restrict__ pc)
{
    __shared__ ull        SA2[32 * 64];      // 16 KB
    __shared__ ulonglong2 SB4[32 * 16];      // 8 KB
    __shared__ ull        DJ[16][6];         // 768 B
    __shared__ float4     dS[NP];
    __shared__ float      ekA[NP];
    __shared__ float      red[8];

    int t = threadIdx.x;
    int k = t & 63;
    const ull H05 = pk2(0.5f, 0.5f);

    for (int tile = blockIdx.x; tile < NTILES; tile += GRID_C) {
        int jh = tile & 1;
        int i  = (tile >> 1) & 63;
        int b  = tile >> 7;
        int j0g = jh * 32;                   // global j offset

        const float* E0r = &g_E[0][b][i * 64];
        const float* E2r = &g_E[2][b][i * 64];
        const float* E3b = g_E[3][b];
        const float* E4b = g_E[4][b];

        float* SA2f = reinterpret_cast<float*>(SA2);
        float* SB4f = reinterpret_cast<float*>(SB4);

        // ---- build (2048 elements each for SA/SB) ----
        for (int idx = t; idx < 32 * 64; idx += 256) {
            int jl = idx >> 6, c = idx & 63;
            int jg = j0g + jl;
            float av = E3b[(jg << 6) + c] + E0r[jg];
            SA2f[(jl << 7) + (c << 1) + 0] = av;
            SA2f[(jl << 7) + (c << 1) + 1] = av;
            float bv = E4b[(jg << 6) + c] + E2r[c];
            SB4f[(jl << 6) + c] = bv;
        }
        if (t < 64) {
            ekA[t] = g_E[1][b][i * 64 + t];
            float ix = pc[b * 192 + i * 3 + 0];
            float iy = pc[b * 192 + i * 3 + 1];
            float iz = pc[b * 192 + i * 3 + 2];
            float dx = pc[b * 192 + t * 3 + 0] - ix;
            float dy = pc[b * 192 + t * 3 + 1] - iy;
            float dz = pc[b * 192 + t * 3 + 2] - iz;
            dS[t] = make_float4(dx, dy, dz, 0.f);
        }
        __syncthreads();
        if (t < 16) {
            int jg0 = j0g + 2 * t, jg1 = jg0 + 1;
            float4 d0 = dS[jg0 & 63], d1 = dS[jg1 & 63];
            // NOTE: dS indexed by point id (0..63); local j maps to global point
            d0 = dS[jg0]; d1 = dS[jg1];
            DJ[t][0] = pk2(d0.x, d0.x);
            DJ[t][1] = pk2(d0.y, d0.y);
            DJ[t][2] = pk2(d0.z, d0.z);
            DJ[t][3] = pk2(d1.x, d1.x);
            DJ[t][4] = pk2(d1.y, d1.y);
            DJ[t][5] = pk2(d1.z, d1.z);
        }
        __syncthreads();

        const float* E5b = g_E[5][b];        // [l][k]
        ull accP = pk2(0.f, 0.f);
        ull accQ = pk2(0.f, 0.f);
        const ull* SA2k = SA2 + k;

        #pragma unroll 1
        for (int u = 0; u < 4; u++) {
            int lq = u * 4 + (t >> 6);
            int l0 = lq * 4;

            float4 dk = dS[k];
            float4 dA = dS[l0 + 0];
            float4 dB = dS[l0 + 1];
            float4 dC = dS[l0 + 2];
            float4 dD = dS[l0 + 3];

            ull cx01 = pk2(dk.y * dA.z - dk.z * dA.y, dk.y * dB.z - dk.z * dB.y);
            ull cy01 = pk2(dk.z * dA.x - dk.x * dA.z, dk.z * dB.x - dk.x * dB.z);
            ull cz01 = pk2(dk.x * dA.y - dk.y * dA.x, dk.x * dB.y - dk.y * dB.x);
            ull cx23 = pk2(dk.y * dC.z - dk.z * dC.y, dk.y * dD.z - dk.z * dD.y);
            ull cy23 = pk2(dk.z * dC.x - dk.x * dC.z, dk.z * dD.x - dk.x * dD.z);
            ull cz23 = pk2(dk.x * dC.y - dk.y * dC.x, dk.x * dD.y - dk.y * dD.x);

            float ekk = ekA[k];
            ull ecA = pk2(ekk + E5b[(l0 + 0) * 64 + k], ekk + E5b[(l0 + 1) * 64 + k]);
            ull ecB = pk2(ekk + E5b[(l0 + 2) * 64 + k], ekk + E5b[(l0 + 3) * 64 + k]);

            const ulonglong2* SB4l = SB4 + lq;

            #pragma unroll 2
            for (int jp = 0; jp < 16; jp++) {
                ull a0r = SA2k[(2 * jp) << 6];
                ull a1r = SA2k[(2 * jp + 1) << 6];
                ulonglong2 b0 = SB4l[(2 * jp) << 4];
                ulonglong2 b1 = SB4l[(2 * jp + 1) << 4];
                ulonglong2 dxy0 = *reinterpret_cast<const ulonglong2*>(&DJ[jp][0]);
                ulonglong2 dzx1 = *reinterpret_cast<const ulonglong2*>(&DJ[jp][2]);
                ulonglong2 dyz1 = *reinterpret_cast<const ulonglong2*>(&DJ[jp][4]);

                // j0
                {
                    ull eP = add2(add2(a0r, b0.x), ecA);
                    ull eQ = add2(add2(a0r, b0.y), ecB);
                    ull detP = fma2(cx01, dxy0.x, fma2(cy01, dxy0.y, mul2(cz01, dzx1.x)));
                    ull detQ = fma2(cx23, dxy0.x, fma2(cy23, dxy0.y, mul2(cz23, dzx1.x)));
                    ull ddP = mul2(detP, detP);
                    ull ddQ = mul2(detQ, detQ);
                    float p0, p1, q0, q1;
                    upk2(eP, p0, p1); upk2(eQ, q0, q1);
                    ull thP = pk2(tanhax(p0), tanhax(p1));
                    ull thQ = pk2(tanhax(q0), tanhax(q1));
                    ull gP = fma2(thP, H05, H05);
                    ull gQ = fma2(thQ, H05, H05);
                    accP = fma2(ddP, gP, accP);
                    accQ = fma2(ddQ, gQ, accQ);
                }
                // j1
                {
                    ull eP = add2(add2(a1r, b1.x), ecA);
                    ull eQ = add2(add2(a1r, b1.y), ecB);
                    ull detP = fma2(cx01, dzx1.y, fma2(cy01, dyz1.x, mul2(cz01, dyz1.y)));
                    ull detQ = fma2(cx23, dzx1.y, fma2(cy23, dyz1.x, mul2(cz23, dyz1.y)));
                    ull ddP = mul2(detP, detP);
                    ull ddQ = mul2(detQ, detQ);
                    float p0, p1, q0, q1;
                    upk2(eP, p0, p1); upk2(eQ, q0, q1);
                    ull thP = pk2(tanhax(p0), tanhax(p1));
                    ull thQ = pk2(tanhax(q0), tanhax(q1));
                    ull gP = fma2(thP, H05, H05);
                    ull gQ = fma2(thQ, H05, H05);
                    accP = fma2(ddP, gP, accP);
                    accQ = fma2(ddQ, gQ, accQ);
                }
            }
        }

        // ---- per-tile reduction (deterministic) ----
        float a0, a1, b0_, b1_;
        upk2(accP, a0, a1); upk2(accQ, b0_, b1_);
        float v = (a0 + a1) + (b0_ + b1_);
        #pragma unroll
        for (int off = 16; off > 0; off >>= 1)
            v += __shfl_xor_sync(0xFFFFFFFFu, v, off);
        if ((t & 31) == 0) red[t >> 5] = v;
        __syncthreads();
        if (t == 0) {
            float s = 0.f;
            #pragma unroll
            for (int w = 0; w < 8; w++) s += red[w];
            g_anchor[jh][b * 64 + i] = s;
        }
        __syncthreads();   // protect SA2/SB4/dS before next tile's build
    }
}

// ---------------------------------------------------------------------------
// Kernel D: grid=32, 128 threads. Sum 128 partials (64 i x 2 jh), MLP head.
// ---------------------------------------------------------------------------
__global__ void kD(const float* __restrict__ W1, const float* __restrict__ b1,
                   const float* __restrict__ W2, const float* __restrict__ b2,
                   float* __restrict__ out)
{
    int b = blockIdx.x, t = threadIdx.x;
    __shared__ float sred[4];
    float v = g_anchor[t >> 6][b * 64 + (t & 63)];
    #pragma unroll
    for (int off = 16; off > 0; off >>= 1)
        v += __shfl_xor_sync(0xFFFFFFFFu, v, off);
    if ((t & 31) == 0) sred[t >> 5] = v;
    __syncthreads();
    if (t < 32) {
        float s = (sred[0] + sred[1] + sred[2] + sred[3]) * (1.0f / 16777216.0f);
        float x = s * W1[t] + b1[t];
        float u = 0.7978845608028654f * (x + 0.044715f * x * x * x);
        float h = 0.5f * x * (1.0f + tanhf(u));
        float c = h * W2[t];
        #pragma unroll
        for (int off = 16; off > 0; off >>= 1)
            c += __shfl_xor_sync(0xFFFFFFFFu, c, off);
        if (t == 0) out[b] = c + b2[0];
    }
}

// ---------------------------------------------------------------------------
extern "C" void kernel_launch(void* const* d_in, const int* in_sizes, int n_in,
                              void* d_out, int out_size)
{
    const float* pc  = (const float*)d_in[0];
    const float* Wq  = (const float*)d_in[1];
    const float* bq  = (const float*)d_in[2];
    const float* Wk1 = (const float*)d_in[3];
    const float* bk1 = (const float*)d_in[4];
    const float* Wk2 = (const float*)d_in[5];
    const float* bk2 = (const float*)d_in[6];
    const float* Wk3 = (const float*)d_in[7];
    const float* bk3 = (const float*)d_in[8];
    const float* W1  = (const float*)d_in[9];
    const float* b1  = (const float*)d_in[10];
    const float* W2  = (const float*)d_in[11];
    const float* b2  = (const float*)d_in[12];
    float* out = (float*)d_out;

    kA<<<BSZ, 256>>>(pc, Wq, bq, Wk1, bk1, Wk2, bk2, Wk3, bk3);
    kB<<<dim3(6, BSZ), 256>>>();
    kC<<<GRID_C, 256>>>(pc);
    kD<<<BSZ, 128>>>(W1, b1, W2, b2, out);
}

// round 5
// speedup vs baseline: 1.0689x; 1.0689x over previous
#include <cuda_runtime.h>
#include <cuda_bf16.h>

// ---------------------------------------------------------------------------
// Simplex4Net: B=32, N=64, D=64
//   kA: projections; kB: six Gram matrices * 0.0625
//   kC: grid (i=64, b=32), full tile per block, occ-2 forced via smem padding
//   kD: reduce + gelu MLP head
// ---------------------------------------------------------------------------

#define BSZ 32
#define NP  64
#define DD  64

__device__ float g_K[4][BSZ][NP * DD];
__device__ float g_E[6][BSZ][NP * NP];   // 0:(i,j) 1:(i,k) 2:(i,l) 3:(j,k) 4:(j,l) 5:(l,k)^T
__device__ float g_anchor[BSZ * NP];

typedef unsigned long long ull;

__device__ __forceinline__ ull pk2(float lo, float hi) {
    ull r; asm("mov.b64 %0, {%1, %2};" : "=l"(r) : "f"(lo), "f"(hi)); return r;
}
__device__ __forceinline__ void upk2(ull v, float& lo, float& hi) {
    asm("mov.b64 {%0, %1}, %2;" : "=f"(lo), "=f"(hi) : "l"(v));
}
__device__ __forceinline__ ull add2(ull a, ull b) {
    ull r; asm("add.rn.f32x2 %0, %1, %2;" : "=l"(r) : "l"(a), "l"(b)); return r;
}
__device__ __forceinline__ ull mul2(ull a, ull b) {
    ull r; asm("mul.rn.f32x2 %0, %1, %2;" : "=l"(r) : "l"(a), "l"(b)); return r;
}
__device__ __forceinline__ ull fma2(ull a, ull b, ull c) {
    ull r; asm("fma.rn.f32x2 %0, %1, %2, %3;" : "=l"(r) : "l"(a), "l"(b), "l"(c)); return r;
}
__device__ __forceinline__ float tanhax(float x) {
    float y; asm("tanh.approx.f32 %0, %1;" : "=f"(y) : "f"(x)); return y;
}

// ---------------------------------------------------------------------------
__global__ void kA(const float* __restrict__ pc,
                   const float* __restrict__ Wq,  const float* __restrict__ bq,
                   const float* __restrict__ Wk1, const float* __restrict__ bk1,
                   const float* __restrict__ Wk2, const float* __restrict__ bk2,
                   const float* __restrict__ Wk3, const float* __restrict__ bk3)
{
    int b = blockIdx.x;
    __shared__ float sp[NP * 3];
    __shared__ float sW[4][3 * DD];
    __shared__ float sb[4][DD];
    int t = threadIdx.x;
    if (t < 192) {
        sp[t]    = pc[b * 192 + t];
        sW[0][t] = Wq[t];
        sW[1][t] = Wk1[t];
        sW[2][t] = Wk2[t];
        sW[3][t] = Wk3[t];
    }
    if (t < 64) {
        sb[0][t] = bq[t]; sb[1][t] = bk1[t]; sb[2][t] = bk2[t]; sb[3][t] = bk3[t];
    }
    __syncthreads();
    for (int m = 0; m < 4; m++) {
        const float* W = sW[m];
        const float* bb = sb[m];
        for (int idx = t; idx < NP * DD; idx += 256) {
            int n = idx >> 6, d = idx & 63;
            float v = bb[d]
                    + sp[n * 3 + 0] * W[d]
                    + sp[n * 3 + 1] * W[64 + d]
                    + sp[n * 3 + 2] * W[128 + d];
            g_K[m][b][idx] = v;
        }
    }
}

// ---------------------------------------------------------------------------
__global__ void kB()
{
    int p = blockIdx.x, b = blockIdx.y;
    const int XI[6] = {0, 0, 0, 1, 1, 3};
    const int YI[6] = {1, 2, 3, 2, 3, 2};
    __shared__ float sX[NP][65];
    __shared__ float sY[NP][65];
    int t = threadIdx.x;
    const float* X = g_K[XI[p]][b];
    const float* Y = g_K[YI[p]][b];
    for (int idx = t; idx < NP * DD; idx += 256) {
        sX[idx >> 6][idx & 63] = X[idx];
        sY[idx >> 6][idx & 63] = Y[idx];
    }
    __syncthreads();
    for (int idx = t; idx < NP * NP; idx += 256) {
        int n = idx >> 6, m = idx & 63;
        float s = 0.f;
        #pragma unroll
        for (int d = 0; d < DD; d++)
            s = fmaf(sX[n][d], sY[m][d], s);
        g_E[p][b][idx] = s * 0.0625f;
    }
}

// ---------------------------------------------------------------------------
// Kernel C: grid=(i=64,b=32), 256 threads. Thread = (k = t&63, l-quad).
// 4 units: lq = u*4 + (t>>6). Inner loop jp (2 j's), 2 packed streams.
// Occupancy forced to 2 blocks/SM via PAD (>76KB static smem): 2048 tiles /
// 296 slots = 6.92 -> 7 waves -> 1.2% tail waste (vs 8-13% at occ 3-4).
// ---------------------------------------------------------------------------
__global__ void __launch_bounds__(256) kC(const float* __restrict__ pc)
{
    __shared__ ull        SA2[64 * 64];      // 32 KB  {a,a} pairs
    __shared__ ulonglong2 SB4[64 * 16];      // 16 KB  b quads
    __shared__ ull        DJ[32][6];         // 1.5 KB
    __shared__ float4     dS[NP];
    __shared__ float      ekA[NP];
    __shared__ float      red[8];
    __shared__ ull        PAD[3072];         // 24 KB occupancy limiter (never written)

    int i = blockIdx.x, b = blockIdx.y, t = threadIdx.x;
    if (pc == (const float*)1) ((volatile ull*)PAD)[0] = 1;  // keep PAD live

    const float* E0r = &g_E[0][b][i * 64];
    const float* E2r = &g_E[2][b][i * 64];
    const float* E3b = g_E[3][b];
    const float* E4b = g_E[4][b];

    float* SA2f = reinterpret_cast<float*>(SA2);
    float* SB4f = reinterpret_cast<float*>(SB4);

    for (int idx = t; idx < NP * NP; idx += 256) {
        int j = idx >> 6, c = idx & 63;
        float av = E3b[idx] + E0r[j];
        SA2f[(j << 7) + (c << 1) + 0] = av;
        SA2f[(j << 7) + (c << 1) + 1] = av;
        float bv = E4b[idx] + E2r[c];
        SB4f[(j << 6) + c] = bv;
    }
    if (t < 64) {
        ekA[t] = g_E[1][b][i * 64 + t];
        float ix = pc[b * 192 + i * 3 + 0];
        float iy = pc[b * 192 + i * 3 + 1];
        float iz = pc[b * 192 + i * 3 + 2];
        float dx = pc[b * 192 + t * 3 + 0] - ix;
        float dy = pc[b * 192 + t * 3 + 1] - iy;
        float dz = pc[b * 192 + t * 3 + 2] - iz;
        dS[t] = make_float4(dx, dy, dz, 0.f);
    }
    __syncthreads();
    if (t < 32) {
        float4 d0 = dS[2 * t], d1 = dS[2 * t + 1];
        DJ[t][0] = pk2(d0.x, d0.x);
        DJ[t][1] = pk2(d0.y, d0.y);
        DJ[t][2] = pk2(d0.z, d0.z);
        DJ[t][3] = pk2(d1.x, d1.x);
        DJ[t][4] = pk2(d1.y, d1.y);
        DJ[t][5] = pk2(d1.z, d1.z);
    }
    __syncthreads();

    const float* E5b = g_E[5][b];            // [l][k]
    const ull H05 = pk2(0.5f, 0.5f);
    ull accP = pk2(0.f, 0.f);
    ull accQ = pk2(0.f, 0.f);

    int k = t & 63;
    const ull* SA2k = SA2 + k;
    float4 dk = dS[k];                       // hoisted: constant across units
    float ekk = ekA[k];

    #pragma unroll 1
    for (int u = 0; u < 4; u++) {
        int lq = u * 4 + (t >> 6);
        int l0 = lq * 4;

        float4 dA = dS[l0 + 0];
        float4 dB = dS[l0 + 1];
        float4 dC = dS[l0 + 2];
        float4 dD = dS[l0 + 3];

        ull cx01 = pk2(dk.y * dA.z - dk.z * dA.y, dk.y * dB.z - dk.z * dB.y);
        ull cy01 = pk2(dk.z * dA.x - dk.x * dA.z, dk.z * dB.x - dk.x * dB.z);
        ull cz01 = pk2(dk.x * dA.y - dk.y * dA.x, dk.x * dB.y - dk.y * dB.x);
        ull cx23 = pk2(dk.y * dC.z - dk.z * dC.y, dk.y * dD.z - dk.z * dD.y);
        ull cy23 = pk2(dk.z * dC.x - dk.x * dC.z, dk.z * dD.x - dk.x * dD.z);
        ull cz23 = pk2(dk.x * dC.y - dk.y * dC.x, dk.x * dD.y - dk.y * dD.x);

        ull ecA = pk2(ekk + E5b[(l0 + 0) * 64 + k], ekk + E5b[(l0 + 1) * 64 + k]);
        ull ecB = pk2(ekk + E5b[(l0 + 2) * 64 + k], ekk + E5b[(l0 + 3) * 64 + k]);

        const ulonglong2* SB4l = SB4 + lq;

        #pragma unroll 4
        for (int jp = 0; jp < 32; jp++) {
            ull a0r = SA2k[(2 * jp) << 6];               // LDS.64 {a,a}
            ull a1r = SA2k[(2 * jp + 1) << 6];
            ulonglong2 b0 = SB4l[(2 * jp) << 4];         // LDS.128 broadcast
            ulonglong2 b1 = SB4l[(2 * jp + 1) << 4];
            ulonglong2 dxy0 = *reinterpret_cast<const ulonglong2*>(&DJ[jp][0]);
            ulonglong2 dzx1 = *reinterpret_cast<const ulonglong2*>(&DJ[jp][2]);
            ulonglong2 dyz1 = *reinterpret_cast<const ulonglong2*>(&DJ[jp][4]);

            // ---- j0 = 2jp ----
            {
                ull eP = add2(add2(a0r, b0.x), ecA);
                ull eQ = add2(add2(a0r, b0.y), ecB);
                ull detP = fma2(cx01, dxy0.x, fma2(cy01, dxy0.y, mul2(cz01, dzx1.x)));
                ull detQ = fma2(cx23, dxy0.x, fma2(cy23, dxy0.y, mul2(cz23, dzx1.x)));
                ull ddP = mul2(detP, detP);
                ull ddQ = mul2(detQ, detQ);
                float p0, p1, q0, q1;
                upk2(eP, p0, p1); upk2(eQ, q0, q1);
                ull thP = pk2(tanhax(p0), tanhax(p1));
                ull thQ = pk2(tanhax(q0), tanhax(q1));
                ull gP = fma2(thP, H05, H05);
                ull gQ = fma2(thQ, H05, H05);
                accP = fma2(ddP, gP, accP);
                accQ = fma2(ddQ, gQ, accQ);
            }
            // ---- j1 = 2jp+1 ----
            {
                ull eP = add2(add2(a1r, b1.x), ecA);
                ull eQ = add2(add2(a1r, b1.y), ecB);
                ull detP = fma2(cx01, dzx1.y, fma2(cy01, dyz1.x, mul2(cz01, dyz1.y)));
                ull detQ = fma2(cx23, dzx1.y, fma2(cy23, dyz1.x, mul2(cz23, dyz1.y)));
                ull ddP = mul2(detP, detP);
                ull ddQ = mul2(detQ, detQ);
                float p0, p1, q0, q1;
                upk2(eP, p0, p1); upk2(eQ, q0, q1);
                ull thP = pk2(tanhax(p0), tanhax(p1));
                ull thQ = pk2(tanhax(q0), tanhax(q1));
                ull gP = fma2(thP, H05, H05);
                ull gQ = fma2(thQ, H05, H05);
                accP = fma2(ddP, gP, accP);
                accQ = fma2(ddQ, gQ, accQ);
            }
        }
    }

    float a0, a1, b0_, b1_;
    upk2(accP, a0, a1); upk2(accQ, b0_, b1_);
    float v = (a0 + a1) + (b0_ + b1_);
    #pragma unroll
    for (int off = 16; off > 0; off >>= 1)
        v += __shfl_xor_sync(0xFFFFFFFFu, v, off);
    if ((t & 31) == 0) red[t >> 5] = v;
    __syncthreads();
    if (t == 0) {
        float s = 0.f;
        #pragma unroll
        for (int w = 0; w < 8; w++) s += red[w];
        g_anchor[b * 64 + i] = s;
    }
}

// ---------------------------------------------------------------------------
__global__ void kD(const float* __restrict__ W1, const float* __restrict__ b1,
                   const float* __restrict__ W2, const float* __restrict__ b2,
                   float* __restrict__ out)
{
    int b = blockIdx.x, t = threadIdx.x;
    __shared__ float sred[2];
    float w1 = (t < 32) ? W1[t] : 0.f;      // prefetch weights before reduce
    float bb1 = (t < 32) ? b1[t] : 0.f;
    float w2 = (t < 32) ? W2[t] : 0.f;
    float v = g_anchor[b * 64 + t];
    #pragma unroll
    for (int off = 16; off > 0; off >>= 1)
        v += __shfl_xor_sync(0xFFFFFFFFu, v, off);
    if ((t & 31) == 0) sred[t >> 5] = v;
    __syncthreads();
    if (t < 32) {
        float s = (sred[0] + sred[1]) * (1.0f / 16777216.0f);
        float x = s * w1 + bb1;
        float u = 0.7978845608028654f * (x + 0.044715f * x * x * x);
        float h = 0.5f * x * (1.0f + tanhf(u));
        float c = h * w2;
        #pragma unroll
        for (int off = 16; off > 0; off >>= 1)
            c += __shfl_xor_sync(0xFFFFFFFFu, c, off);
        if (t == 0) out[b] = c + b2[0];
    }
}

// ---------------------------------------------------------------------------
extern "C" void kernel_launch(void* const* d_in, const int* in_sizes, int n_in,
                              void* d_out, int out_size)
{
    const float* pc  = (const float*)d_in[0];
    const float* Wq  = (const float*)d_in[1];
    const float* bq  = (const float*)d_in[2];
    const float* Wk1 = (const float*)d_in[3];
    const float* bk1 = (const float*)d_in[4];
    const float* Wk2 = (const float*)d_in[5];
    const float* bk2 = (const float*)d_in[6];
    const float* Wk3 = (const float*)d_in[7];
    const float* bk3 = (const float*)d_in[8];
    const float* W1  = (const float*)d_in[9];
    const float* b1  = (const float*)d_in[10];
    const float* W2  = (const float*)d_in[11];
    const float* b2  = (const float*)d_in[12];
    float* out = (float*)d_out;

    kA<<<BSZ, 256>>>(pc, Wq, bq, Wk1, bk1, Wk2, bk2, Wk3, bk3);
    kB<<<dim3(6, BSZ), 256>>>();
    kC<<<dim3(NP, BSZ), 256>>>(pc);
    kD<<<BSZ, 64>>>(W1, b1, W2, b2, out);
}

// round 6
// speedup vs baseline: 1.1471x; 1.0732x over previous
#include <cuda_runtime.h>
#include <cuda_bf16.h>

// ---------------------------------------------------------------------------
// Simplex4Net: B=32, N=64, D=64
//   kA: projections; kB: six Gram matrices * 0.0625
//   kC: grid (i=64, b=32), occ-3 via smem padding; gate split:
//       sigma(E)*det^2 = 0.5*det^2 + 0.5*det^2*tanh(E/2); the ungated part
//       is closed-form via S = sum_j d_j d_j^T  -> inner loop is 7 FMA ops/el
//   kD: reduce + gelu MLP head
// ---------------------------------------------------------------------------

#define BSZ 32
#define NP  64
#define DD  64

__device__ float g_K[4][BSZ][NP * DD];
__device__ float g_E[6][BSZ][NP * NP];   // 0:(i,j) 1:(i,k) 2:(i,l) 3:(j,k) 4:(j,l) 5:(l,k)^T
__device__ float g_anchor[BSZ * NP];

typedef unsigned long long ull;

__device__ __forceinline__ ull pk2(float lo, float hi) {
    ull r; asm("mov.b64 %0, {%1, %2};" : "=l"(r) : "f"(lo), "f"(hi)); return r;
}
__device__ __forceinline__ void upk2(ull v, float& lo, float& hi) {
    asm("mov.b64 {%0, %1}, %2;" : "=f"(lo), "=f"(hi) : "l"(v));
}
__device__ __forceinline__ ull add2(ull a, ull b) {
    ull r; asm("add.rn.f32x2 %0, %1, %2;" : "=l"(r) : "l"(a), "l"(b)); return r;
}
__device__ __forceinline__ ull mul2(ull a, ull b) {
    ull r; asm("mul.rn.f32x2 %0, %1, %2;" : "=l"(r) : "l"(a), "l"(b)); return r;
}
__device__ __forceinline__ ull fma2(ull a, ull b, ull c) {
    ull r; asm("fma.rn.f32x2 %0, %1, %2, %3;" : "=l"(r) : "l"(a), "l"(b), "l"(c)); return r;
}
__device__ __forceinline__ float tanhax(float x) {
    float y; asm("tanh.approx.f32 %0, %1;" : "=f"(y) : "f"(x)); return y;
}

// ---------------------------------------------------------------------------
__global__ void kA(const float* __restrict__ pc,
                   const float* __restrict__ Wq,  const float* __restrict__ bq,
                   const float* __restrict__ Wk1, const float* __restrict__ bk1,
                   const float* __restrict__ Wk2, const float* __restrict__ bk2,
                   const float* __restrict__ Wk3, const float* __restrict__ bk3)
{
    int b = blockIdx.x;
    __shared__ float sp[NP * 3];
    __shared__ float sW[4][3 * DD];
    __shared__ float sb[4][DD];
    int t = threadIdx.x;
    if (t < 192) {
        sp[t]    = pc[b * 192 + t];
        sW[0][t] = Wq[t];
        sW[1][t] = Wk1[t];
        sW[2][t] = Wk2[t];
        sW[3][t] = Wk3[t];
    }
    if (t < 64) {
        sb[0][t] = bq[t]; sb[1][t] = bk1[t]; sb[2][t] = bk2[t]; sb[3][t] = bk3[t];
    }
    __syncthreads();
    for (int m = 0; m < 4; m++) {
        const float* W = sW[m];
        const float* bb = sb[m];
        for (int idx = t; idx < NP * DD; idx += 256) {
            int n = idx >> 6, d = idx & 63;
            float v = bb[d]
                    + sp[n * 3 + 0] * W[d]
                    + sp[n * 3 + 1] * W[64 + d]
                    + sp[n * 3 + 2] * W[128 + d];
            g_K[m][b][idx] = v;
        }
    }
}

// ---------------------------------------------------------------------------
__global__ void kB()
{
    int p = blockIdx.x, b = blockIdx.y;
    const int XI[6] = {0, 0, 0, 1, 1, 3};
    const int YI[6] = {1, 2, 3, 2, 3, 2};
    __shared__ float sX[NP][65];
    __shared__ float sY[NP][65];
    int t = threadIdx.x;
    const float* X = g_K[XI[p]][b];
    const float* Y = g_K[YI[p]][b];
    for (int idx = t; idx < NP * DD; idx += 256) {
        sX[idx >> 6][idx & 63] = X[idx];
        sY[idx >> 6][idx & 63] = Y[idx];
    }
    __syncthreads();
    for (int idx = t; idx < NP * NP; idx += 256) {
        int n = idx >> 6, m = idx & 63;
        float s = 0.f;
        #pragma unroll
        for (int d = 0; d < DD; d++)
            s = fmaf(sX[n][d], sY[m][d], s);
        g_E[p][b][idx] = s * 0.0625f;
    }
}

// ---------------------------------------------------------------------------
// Kernel C: grid=(i=64,b=32), 256 threads, occ-3 (smem pad to ~58KB).
// Thread = (k = t&63, l-quad per unit). Inner jp loop covers 2 j's.
// ---------------------------------------------------------------------------
__global__ void __launch_bounds__(256, 3) kC(const float* __restrict__ pc)
{
    __shared__ ull        SA2[64 * 64];      // 32 KB  {a,a}
    __shared__ ulonglong2 SB4[64 * 16];      // 16 KB
    __shared__ ull        DJ[32][6];         // 1.5 KB
    __shared__ float4     dS[NP];            // 1 KB
    __shared__ float      ekA[NP];
    __shared__ float      sS[6];             // S = sum_j d_j d_j^T (xx,yy,zz,xy,xz,yz)
    __shared__ float      red[8];
    __shared__ ull        PAD[768];          // 6 KB occupancy limiter -> occ 3

    int i = blockIdx.x, b = blockIdx.y, t = threadIdx.x;
    if (pc == (const float*)1) ((volatile ull*)PAD)[0] = 1;   // keep PAD live

    const float* E0r = &g_E[0][b][i * 64];
    const float* E2r = &g_E[2][b][i * 64];
    const float* E3b = g_E[3][b];
    const float* E4b = g_E[4][b];

    float* SA2f = reinterpret_cast<float*>(SA2);
    float* SB4f = reinterpret_cast<float*>(SB4);

    for (int idx = t; idx < NP * NP; idx += 256) {
        int j = idx >> 6, c = idx & 63;
        float av = E3b[idx] + E0r[j];
        SA2f[(j << 7) + (c << 1) + 0] = av;
        SA2f[(j << 7) + (c << 1) + 1] = av;
        float bv = E4b[idx] + E2r[c];
        SB4f[(j << 6) + c] = bv;
    }
    if (t < 64) {
        ekA[t] = g_E[1][b][i * 64 + t];
        float ix = pc[b * 192 + i * 3 + 0];
        float iy = pc[b * 192 + i * 3 + 1];
        float iz = pc[b * 192 + i * 3 + 2];
        float dx = pc[b * 192 + t * 3 + 0] - ix;
        float dy = pc[b * 192 + t * 3 + 1] - iy;
        float dz = pc[b * 192 + t * 3 + 2] - iz;
        dS[t] = make_float4(dx, dy, dz, 0.f);
    }
    __syncthreads();
    if (t < 32) {
        float4 d0 = dS[2 * t], d1 = dS[2 * t + 1];
        DJ[t][0] = pk2(d0.x, d0.x);
        DJ[t][1] = pk2(d0.y, d0.y);
        DJ[t][2] = pk2(d0.z, d0.z);
        DJ[t][3] = pk2(d1.x, d1.x);
        DJ[t][4] = pk2(d1.y, d1.y);
        DJ[t][5] = pk2(d1.z, d1.z);
    } else if (t < 38) {
        // S matrix: 6 entries, one per thread
        int e = t - 32;
        int c1 = (e == 0 || e == 3 || e == 4) ? 0 : (e == 1 || e == 5) ? 1 : 2;
        int c2 = (e == 0) ? 0 : (e == 1 || e == 3) ? 1 : (e == 5 || e == 4 || e == 2) ? ((e == 4 || e == 2) ? 2 : 1) : 2;
        // explicit: pairs (0,0),(1,1),(2,2),(0,1),(0,2),(1,2)
        if (e == 3) { c1 = 0; c2 = 1; }
        if (e == 4) { c1 = 0; c2 = 2; }
        if (e == 5) { c1 = 1; c2 = 2; }
        float s = 0.f;
        for (int j = 0; j < 64; j++) {
            const float* dp = reinterpret_cast<const float*>(&dS[j]);
            s = fmaf(dp[c1], dp[c2], s);
        }
        sS[e] = s;
    }
    __syncthreads();

    const float* E5b = g_E[5][b];            // [l][k]
    ull accP = pk2(0.f, 0.f);
    ull accQ = pk2(0.f, 0.f);
    float qsum = 0.f;

    int k = t & 63;
    const ull* SA2k = SA2 + k;
    float4 dk = dS[k];
    float ekk = ekA[k];
    float Sxx = sS[0], Syy = sS[1], Szz = sS[2];
    float Sxy2 = 2.f * sS[3], Sxz2 = 2.f * sS[4], Syz2 = 2.f * sS[5];

    #pragma unroll 1
    for (int u = 0; u < 4; u++) {
        int lq = u * 4 + (t >> 6);
        int l0 = lq * 4;

        float4 dA = dS[l0 + 0];
        float4 dB = dS[l0 + 1];
        float4 dC = dS[l0 + 2];
        float4 dD = dS[l0 + 3];

        float cAx = dk.y * dA.z - dk.z * dA.y, cAy = dk.z * dA.x - dk.x * dA.z, cAz = dk.x * dA.y - dk.y * dA.x;
        float cBx = dk.y * dB.z - dk.z * dB.y, cBy = dk.z * dB.x - dk.x * dB.z, cBz = dk.x * dB.y - dk.y * dB.x;
        float cCx = dk.y * dC.z - dk.z * dC.y, cCy = dk.z * dC.x - dk.x * dC.z, cCz = dk.x * dC.y - dk.y * dC.x;
        float cDx = dk.y * dD.z - dk.z * dD.y, cDy = dk.z * dD.x - dk.x * dD.z, cDz = dk.x * dD.y - dk.y * dD.x;

        // closed-form ungated part: sum_j (c . d_j)^2 = c^T S c
        {
            float qA = cAx * (fmaf(Sxy2, cAy, fmaf(Sxz2, cAz, Sxx * cAx)))
                     + cAy * fmaf(Syz2, cAz, Syy * cAy) + cAz * cAz * Szz;
            float qB = cBx * (fmaf(Sxy2, cBy, fmaf(Sxz2, cBz, Sxx * cBx)))
                     + cBy * fmaf(Syz2, cBz, Syy * cBy) + cBz * cBz * Szz;
            float qC = cCx * (fmaf(Sxy2, cCy, fmaf(Sxz2, cCz, Sxx * cCx)))
                     + cCy * fmaf(Syz2, cCz, Syy * cCy) + cCz * cCz * Szz;
            float qD = cDx * (fmaf(Sxy2, cDy, fmaf(Sxz2, cDz, Sxx * cDx)))
                     + cDy * fmaf(Syz2, cDz, Syy * cDy) + cDz * cDz * Szz;
            qsum += (qA + qB) + (qC + qD);
        }

        ull cx01 = pk2(cAx, cBx), cy01 = pk2(cAy, cBy), cz01 = pk2(cAz, cBz);
        ull cx23 = pk2(cCx, cDx), cy23 = pk2(cCy, cDy), cz23 = pk2(cCz, cDz);

        ull ecA = pk2(ekk + E5b[(l0 + 0) * 64 + k], ekk + E5b[(l0 + 1) * 64 + k]);
        ull ecB = pk2(ekk + E5b[(l0 + 2) * 64 + k], ekk + E5b[(l0 + 3) * 64 + k]);

        const ulonglong2* SB4l = SB4 + lq;

        #pragma unroll 4
        for (int jp = 0; jp < 32; jp++) {
            ull a0r = SA2k[(2 * jp) << 6];
            ull a1r = SA2k[(2 * jp + 1) << 6];
            ulonglong2 b0 = SB4l[(2 * jp) << 4];
            ulonglong2 b1 = SB4l[(2 * jp + 1) << 4];
            ulonglong2 dxy0 = *reinterpret_cast<const ulonglong2*>(&DJ[jp][0]);
            ulonglong2 dzx1 = *reinterpret_cast<const ulonglong2*>(&DJ[jp][2]);
            ulonglong2 dyz1 = *reinterpret_cast<const ulonglong2*>(&DJ[jp][4]);

            // ---- j0 = 2jp ----
            {
                ull eP = add2(add2(a0r, b0.x), ecA);
                ull eQ = add2(add2(a0r, b0.y), ecB);
                ull detP = fma2(cx01, dxy0.x, fma2(cy01, dxy0.y, mul2(cz01, dzx1.x)));
                ull detQ = fma2(cx23, dxy0.x, fma2(cy23, dxy0.y, mul2(cz23, dzx1.x)));
                ull ddP = mul2(detP, detP);
                ull ddQ = mul2(detQ, detQ);
                float p0, p1, q0, q1;
                upk2(eP, p0, p1); upk2(eQ, q0, q1);
                ull thP = pk2(tanhax(p0), tanhax(p1));
                ull thQ = pk2(tanhax(q0), tanhax(q1));
                accP = fma2(ddP, thP, accP);
                accQ = fma2(ddQ, thQ, accQ);
            }
            // ---- j1 = 2jp+1 ----
            {
                ull eP = add2(add2(a1r, b1.x), ecA);
                ull eQ = add2(add2(a1r, b1.y), ecB);
                ull detP = fma2(cx01, dzx1.y, fma2(cy01, dyz1.x, mul2(cz01, dyz1.y)));
                ull detQ = fma2(cx23, dzx1.y, fma2(cy23, dyz1.x, mul2(cz23, dyz1.y)));
                ull ddP = mul2(detP, detP);
                ull ddQ = mul2(detQ, detQ);
                float p0, p1, q0, q1;
                upk2(eP, p0, p1); upk2(eQ, q0, q1);
                ull thP = pk2(tanhax(p0), tanhax(p1));
                ull thQ = pk2(tanhax(q0), tanhax(q1));
                accP = fma2(ddP, thP, accP);
                accQ = fma2(ddQ, thQ, accQ);
            }
        }
    }

    float a0, a1, b0_, b1_;
    upk2(accP, a0, a1); upk2(accQ, b0_, b1_);
    float v = ((a0 + a1) + (b0_ + b1_)) + qsum;   // th-sum + ungated sum
    #pragma unroll
    for (int off = 16; off > 0; off >>= 1)
        v += __shfl_xor_sync(0xFFFFFFFFu, v, off);
    if ((t & 31) == 0) red[t >> 5] = v;
    __syncthreads();
    if (t == 0) {
        float s = 0.f;
        #pragma unroll
        for (int w = 0; w < 8; w++) s += red[w];
        g_anchor[b * 64 + i] = s * 0.5f;
    }
}

// ---------------------------------------------------------------------------
__global__ void kD(const float* __restrict__ W1, const float* __restrict__ b1,
                   const float* __restrict__ W2, const float* __restrict__ b2,
                   float* __restrict__ out)
{
    int b = blockIdx.x, t = threadIdx.x;
    __shared__ float sred[2];
    float w1 = (t < 32) ? W1[t] : 0.f;
    float bb1 = (t < 32) ? b1[t] : 0.f;
    float w2 = (t < 32) ? W2[t] : 0.f;
    float v = g_anchor[b * 64 + t];
    #pragma unroll
    for (int off = 16; off > 0; off >>= 1)
        v += __shfl_xor_sync(0xFFFFFFFFu, v, off);
    if ((t & 31) == 0) sred[t >> 5] = v;
    __syncthreads();
    if (t < 32) {
        float s = (sred[0] + sred[1]) * (1.0f / 16777216.0f);
        float x = s * w1 + bb1;
        float u = 0.7978845608028654f * (x + 0.044715f * x * x * x);
        float h = 0.5f * x * (1.0f + tanhf(u));
        float c = h * w2;
        #pragma unroll
        for (int off = 16; off > 0; off >>= 1)
            c += __shfl_xor_sync(0xFFFFFFFFu, c, off);
        if (t == 0) out[b] = c + b2[0];
    }
}

// ---------------------------------------------------------------------------
extern "C" void kernel_launch(void* const* d_in, const int* in_sizes, int n_in,
                              void* d_out, int out_size)
{
    const float* pc  = (const float*)d_in[0];
    const float* Wq  = (const float*)d_in[1];
    const float* bq  = (const float*)d_in[2];
    const float* Wk1 = (const float*)d_in[3];
    const float* bk1 = (const float*)d_in[4];
    const float* Wk2 = (const float*)d_in[5];
    const float* bk2 = (const float*)d_in[6];
    const float* Wk3 = (const float*)d_in[7];
    const float* bk3 = (const float*)d_in[8];
    const float* W1  = (const float*)d_in[9];
    const float* b1  = (const float*)d_in[10];
    const float* W2  = (const float*)d_in[11];
    const float* b2  = (const float*)d_in[12];
    float* out = (float*)d_out;

    kA<<<BSZ, 256>>>(pc, Wq, bq, Wk1, bk1, Wk2, bk2, Wk3, bk3);
    kB<<<dim3(6, BSZ), 256>>>();
    kC<<<dim3(NP, BSZ), 256>>>(pc);
    kD<<<BSZ, 64>>>(W1, b1, W2, b2, out);
}